// round 1
// baseline (speedup 1.0000x reference)
#include <cuda_runtime.h>
#include <cuda_bf16.h>
#include <float.h>

// Problem constants (fixed shapes for this problem):
//   network_mesh: (4, 3, 32, 32) float32   -> d_in[0], 12288 elems
//   pc:           (4, 3, 4096)   float32   -> d_in[1], 49152 elems
//   output: scalar float32 (mean over 4*4096 nearest-mesh squared distances)
#define B_      4
#define H_      32
#define W_      32
#define FAC_    3
#define OH_     94          // (32-1)*3+1
#define OW_     94
#define NMESH_  (OH_ * OW_) // 8836 mesh points per batch
#define M_      4096        // pc points per batch
#define SLICES_ 9
#define SLICE_  982         // ceil(8836/9)
#define THREADS_ 256
#define RPT_    4           // pc points per thread (256*4 = 1024 pts/block)
#define CHUNKS_ 4           // 4096 / 1024

// Scratch (allocation-free): refined mesh as float4 (x, y, z, |m|^2),
// and per-slice partial minima (already including |p|^2).
__device__ float4 g_mesh[B_ * NMESH_];                 // ~565 KB
__device__ float  g_partial[SLICES_ * B_ * M_];        // ~589 KB

// ---------------------------------------------------------------------------
// Kernel A: bilinear refine (align_corners style, factor 3) + |m|^2 precompute.
// One thread per (b, r, c) output point; computes all 3 channels.
// ---------------------------------------------------------------------------
__global__ void refine_kernel(const float* __restrict__ mesh) {
    int idx = blockIdx.x * blockDim.x + threadIdx.x;
    if (idx >= B_ * OH_ * OW_) return;
    int b  = idx / (OH_ * OW_);
    int rc = idx % (OH_ * OW_);
    int r  = rc / OW_;
    int c  = rc % OW_;

    // y0 = clip(floor(r/3), 0, H-2); wy = r/3 - y0   (matches reference math)
    int y0 = r / FAC_; if (y0 > H_ - 2) y0 = H_ - 2;
    int x0 = c / FAC_; if (x0 > W_ - 2) x0 = W_ - 2;
    float wy = (float)r / (float)FAC_ - (float)y0;
    float wx = (float)c / (float)FAC_ - (float)x0;
    int y1 = y0 + 1, x1 = x0 + 1;

    float v[3];
    float s = 0.0f;
#pragma unroll
    for (int ch = 0; ch < 3; ch++) {
        const float* m = mesh + ((b * 3 + ch) * H_) * W_;
        float g00 = m[y0 * W_ + x0];
        float g01 = m[y0 * W_ + x1];
        float g10 = m[y1 * W_ + x0];
        float g11 = m[y1 * W_ + x1];
        float top = g00 * (1.0f - wx) + g01 * wx;
        float bot = g10 * (1.0f - wx) + g11 * wx;
        v[ch] = top * (1.0f - wy) + bot * wy;
        s = fmaf(v[ch], v[ch], s);
    }
    g_mesh[b * NMESH_ + r * OW_ + c] = make_float4(v[0], v[1], v[2], s);
}

// ---------------------------------------------------------------------------
// Kernel B: per-slice nearest-mesh-point partial minima.
// grid = (B, CHUNKS, SLICES) = (4, 4, 9) = 144 blocks (one wave on 148 SMs).
// Each thread holds RPT_=4 pc points; mesh slice (x,y,z,|m|^2) broadcast from smem.
// t = fma(mx,-2px, fma(my,-2py, fma(mz,-2pz, |m|^2)));  dist2 = min t + |p|^2.
// ---------------------------------------------------------------------------
__global__ __launch_bounds__(THREADS_, 1)
void dist_kernel(const float* __restrict__ pc) {
    __shared__ float4 sm[SLICE_];

    const int b     = blockIdx.x;
    const int chunk = blockIdx.y;
    const int s     = blockIdx.z;

    const int base = s * SLICE_;
    const int cnt  = (base + SLICE_ <= NMESH_) ? SLICE_ : (NMESH_ - base);

    // Stage mesh slice into shared memory.
    for (int i = threadIdx.x; i < cnt; i += THREADS_)
        sm[i] = g_mesh[b * NMESH_ + base + i];
    __syncthreads();

    const float* __restrict__ px = pc + (b * 3 + 0) * M_;
    const float* __restrict__ py = pc + (b * 3 + 1) * M_;
    const float* __restrict__ pz = pc + (b * 3 + 2) * M_;

    const int p0 = chunk * (THREADS_ * RPT_) + threadIdx.x;

    float ax[RPT_], ay[RPT_], az[RPT_], pp[RPT_], best[RPT_];
#pragma unroll
    for (int r = 0; r < RPT_; r++) {
        int m = p0 + r * THREADS_;
        float x = px[m], y = py[m], z = pz[m];
        ax[r] = -2.0f * x;
        ay[r] = -2.0f * y;
        az[r] = -2.0f * z;
        pp[r] = fmaf(x, x, fmaf(y, y, z * z));
        best[r] = FLT_MAX;
    }

#pragma unroll 2
    for (int j = 0; j < cnt; j++) {
        float4 m = sm[j];   // broadcast: all lanes read the same address
#pragma unroll
        for (int r = 0; r < RPT_; r++) {
            float t = fmaf(m.x, ax[r], fmaf(m.y, ay[r], fmaf(m.z, az[r], m.w)));
            best[r] = fminf(best[r], t);
        }
    }

#pragma unroll
    for (int r = 0; r < RPT_; r++) {
        int m = p0 + r * THREADS_;
        g_partial[(s * B_ + b) * M_ + m] = best[r] + pp[r];
    }
}

// ---------------------------------------------------------------------------
// Kernel C: min across slices + deterministic mean reduction (single block).
// ---------------------------------------------------------------------------
__global__ void reduce_kernel(float* __restrict__ out) {
    __shared__ float red[THREADS_];
    const int total = B_ * M_;
    float acc = 0.0f;
    for (int i = threadIdx.x; i < total; i += THREADS_) {
        float v = g_partial[i];
#pragma unroll
        for (int s = 1; s < SLICES_; s++)
            v = fminf(v, g_partial[s * total + i]);
        acc += v;
    }
    red[threadIdx.x] = acc;
    __syncthreads();
#pragma unroll
    for (int off = THREADS_ / 2; off > 0; off >>= 1) {
        if (threadIdx.x < off) red[threadIdx.x] += red[threadIdx.x + off];
        __syncthreads();
    }
    if (threadIdx.x == 0) out[0] = red[0] / (float)total;
}

// ---------------------------------------------------------------------------
extern "C" void kernel_launch(void* const* d_in, const int* in_sizes, int n_in,
                              void* d_out, int out_size) {
    const float* mesh = (const float*)d_in[0];  // (4,3,32,32)
    const float* pc   = (const float*)d_in[1];  // (4,3,4096)
    float* out = (float*)d_out;

    refine_kernel<<<(B_ * OH_ * OW_ + 255) / 256, 256>>>(mesh);

    dim3 grid(B_, CHUNKS_, SLICES_);
    dist_kernel<<<grid, THREADS_>>>(pc);

    reduce_kernel<<<1, THREADS_>>>(out);
}

// round 2
// speedup vs baseline: 1.4937x; 1.4937x over previous
#include <cuda_runtime.h>
#include <float.h>

// Shapes (fixed): network_mesh (4,3,32,32) f32 = d_in[0]; pc (4,3,4096) f32 = d_in[1].
// Output: scalar f32 = mean over 4*4096 nearest-refined-mesh squared distances.
#define B_       4
#define H_       32
#define W_       32
#define FAC_     3
#define OH_      94          // (32-1)*3+1
#define OW_      94
#define NMESH_   (OH_ * OW_) // 8836
#define M_       4096
#define SLICES_  9
#define SLICE_   982         // ceil(8836/9); last slice = 980
#define THREADS_ 256
#define RPT_     2           // pc PAIRS per thread (2 pairs = 4 points)
#define CHUNKS_  4           // 2048 pairs / (256 thr * 2 pairs)
#define R1BLOCKS_ 64

// Allocation-free scratch.
__device__ float g_partial[SLICES_ * B_ * M_];   // per-slice per-point minima (incl |p|^2)
__device__ float g_sums[R1BLOCKS_];

union df2 { unsigned long long u; float2 f; };

__device__ __forceinline__ unsigned long long pack2(float lo, float hi) {
    df2 t; t.f = make_float2(lo, hi); return t.u;
}

// Packed dual-FMA: two f32 lanes in one instruction (Blackwell f32x2 path).
__device__ __forceinline__ unsigned long long fma2(unsigned long long a,
                                                   unsigned long long b,
                                                   unsigned long long c) {
    unsigned long long r;
    asm("fma.rn.f32x2 %0, %1, %2, %3;" : "=l"(r) : "l"(a), "l"(b), "l"(c));
    return r;
}

// ---------------------------------------------------------------------------
// Kernel 1: fused refine (inline, per-slice) + nearest-point partial minima.
// grid = (B, CHUNKS, SLICES) = (4,4,9) = 144 blocks, one wave on 148 SMs.
// smem holds the slice duplicated per lane-pair: sa[j]={xx,yy}, sb[j]={zz,ww}.
// ---------------------------------------------------------------------------
__global__ __launch_bounds__(THREADS_, 1)
void dist_kernel(const float* __restrict__ mesh, const float* __restrict__ pc) {
    __shared__ ulonglong2 sa[SLICE_];   // {x,x},{y,y}
    __shared__ ulonglong2 sb[SLICE_];   // {z,z},{w,w}  w = |m|^2

    const int b     = blockIdx.x;
    const int chunk = blockIdx.y;
    const int s     = blockIdx.z;

    const int base = s * SLICE_;
    const int cnt  = (base + SLICE_ <= NMESH_) ? SLICE_ : (NMESH_ - base);

    // --- Inline bilinear refine (align_corners, factor 3) for this slice ---
    const float* __restrict__ m0 = mesh + (b * 3 + 0) * H_ * W_;
    const float* __restrict__ m1 = mesh + (b * 3 + 1) * H_ * W_;
    const float* __restrict__ m2 = mesh + (b * 3 + 2) * H_ * W_;

    for (int i = threadIdx.x; i < cnt; i += THREADS_) {
        int idx = base + i;
        int r = idx / OW_;
        int c = idx - r * OW_;
        int y0 = r / FAC_; if (y0 > H_ - 2) y0 = H_ - 2;
        int x0 = c / FAC_; if (x0 > W_ - 2) x0 = W_ - 2;
        float wy = (float)r / (float)FAC_ - (float)y0;
        float wx = (float)c / (float)FAC_ - (float)x0;
        int o00 = y0 * W_ + x0, o01 = o00 + 1, o10 = o00 + W_, o11 = o10 + 1;

        float t0 = m0[o00] * (1.0f - wx) + m0[o01] * wx;
        float u0 = m0[o10] * (1.0f - wx) + m0[o11] * wx;
        float v0 = t0 * (1.0f - wy) + u0 * wy;

        float t1 = m1[o00] * (1.0f - wx) + m1[o01] * wx;
        float u1 = m1[o10] * (1.0f - wx) + m1[o11] * wx;
        float v1 = t1 * (1.0f - wy) + u1 * wy;

        float t2 = m2[o00] * (1.0f - wx) + m2[o01] * wx;
        float u2 = m2[o10] * (1.0f - wx) + m2[o11] * wx;
        float v2 = t2 * (1.0f - wy) + u2 * wy;

        float w = fmaf(v0, v0, fmaf(v1, v1, v2 * v2));

        sa[i] = make_ulonglong2(pack2(v0, v0), pack2(v1, v1));
        sb[i] = make_ulonglong2(pack2(v2, v2), pack2(w, w));
    }
    __syncthreads();

    // --- Load this thread's pc point pairs ---
    const float* __restrict__ px = pc + (b * 3 + 0) * M_;
    const float* __restrict__ py = pc + (b * 3 + 1) * M_;
    const float* __restrict__ pz = pc + (b * 3 + 2) * M_;

    const int q0 = chunk * (THREADS_ * RPT_) + threadIdx.x;   // pair index

    unsigned long long ax2[RPT_], ay2[RPT_], az2[RPT_];
    float pp0[RPT_], pp1[RPT_], b0[RPT_], b1[RPT_];
#pragma unroll
    for (int r = 0; r < RPT_; r++) {
        int q = q0 + r * THREADS_;
        float2 x = *(const float2*)(px + 2 * q);
        float2 y = *(const float2*)(py + 2 * q);
        float2 z = *(const float2*)(pz + 2 * q);
        ax2[r] = pack2(-2.0f * x.x, -2.0f * x.y);
        ay2[r] = pack2(-2.0f * y.x, -2.0f * y.y);
        az2[r] = pack2(-2.0f * z.x, -2.0f * z.y);
        pp0[r] = fmaf(x.x, x.x, fmaf(y.x, y.x, z.x * z.x));
        pp1[r] = fmaf(x.y, x.y, fmaf(y.y, y.y, z.y * z.y));
        b0[r] = FLT_MAX;
        b1[r] = FLT_MAX;
    }

    // --- Hot loop: t = fma2(xx,ax, fma2(yy,ay, fma2(zz,az, ww))); min-fold ---
#pragma unroll 4
    for (int j = 0; j < cnt; j++) {
        ulonglong2 A = sa[j];   // broadcast LDS.128
        ulonglong2 Bv = sb[j];
#pragma unroll
        for (int r = 0; r < RPT_; r++) {
            df2 t;
            t.u = fma2(A.x, ax2[r], fma2(A.y, ay2[r], fma2(Bv.x, az2[r], Bv.y)));
            b0[r] = fminf(b0[r], t.f.x);
            b1[r] = fminf(b1[r], t.f.y);
        }
    }

#pragma unroll
    for (int r = 0; r < RPT_; r++) {
        int q = q0 + r * THREADS_;
        float2 out = make_float2(b0[r] + pp0[r], b1[r] + pp1[r]);
        *(float2*)(g_partial + (s * B_ + b) * M_ + 2 * q) = out;
    }
}

// ---------------------------------------------------------------------------
// Kernel 2: per-point min across slices + per-block deterministic tree sum.
// grid = 64 blocks x 256 threads, one point per thread.
// ---------------------------------------------------------------------------
__global__ __launch_bounds__(THREADS_)
void reduce1_kernel() {
    __shared__ float red[THREADS_];
    const int i = blockIdx.x * THREADS_ + threadIdx.x;   // i < 16384
    float v = g_partial[i];
#pragma unroll
    for (int s = 1; s < SLICES_; s++)
        v = fminf(v, g_partial[s * (B_ * M_) + i]);
    red[threadIdx.x] = v;
    __syncthreads();
#pragma unroll
    for (int off = THREADS_ / 2; off > 0; off >>= 1) {
        if (threadIdx.x < off) red[threadIdx.x] += red[threadIdx.x + off];
        __syncthreads();
    }
    if (threadIdx.x == 0) g_sums[blockIdx.x] = red[0];
}

// ---------------------------------------------------------------------------
// Kernel 3: final deterministic sum of 64 partials + mean.
// ---------------------------------------------------------------------------
__global__ void reduce2_kernel(float* __restrict__ out) {
    __shared__ float red[R1BLOCKS_];
    red[threadIdx.x] = g_sums[threadIdx.x];
    __syncthreads();
#pragma unroll
    for (int off = R1BLOCKS_ / 2; off > 0; off >>= 1) {
        if (threadIdx.x < off) red[threadIdx.x] += red[threadIdx.x + off];
        __syncthreads();
    }
    if (threadIdx.x == 0) out[0] = red[0] / (float)(B_ * M_);
}

// ---------------------------------------------------------------------------
extern "C" void kernel_launch(void* const* d_in, const int* in_sizes, int n_in,
                              void* d_out, int out_size) {
    const float* mesh = (const float*)d_in[0];
    const float* pc   = (const float*)d_in[1];
    float* out = (float*)d_out;

    dim3 grid(B_, CHUNKS_, SLICES_);
    dist_kernel<<<grid, THREADS_>>>(mesh, pc);
    reduce1_kernel<<<R1BLOCKS_, THREADS_>>>();
    reduce2_kernel<<<1, R1BLOCKS_>>>(out);
}

// round 3
// speedup vs baseline: 1.5918x; 1.0656x over previous
#include <cuda_runtime.h>
#include <float.h>

// Shapes (fixed): network_mesh (4,3,32,32) f32 = d_in[0]; pc (4,3,4096) f32 = d_in[1].
// Output: scalar f32 = mean over 4*4096 nearest-refined-mesh squared distances.
#define B_       4
#define H_       32
#define W_       32
#define FAC_     3
#define OH_      94          // (32-1)*3+1
#define OW_      94
#define NMESH_   (OH_ * OW_) // 8836
#define M_       4096
#define SLICES_  36
#define SLICE_   246         // ceil(8836/36); last slice = 226
#define THREADS_ 256
#define RPT_     4           // pc point PAIRS per thread (4 pairs = 8 points)
#define CHUNKS_  2           // 4096 pts / (256 thr * 8 pts)
#define R1BLOCKS_ 64

// Allocation-free scratch.
__device__ float g_partial[SLICES_ * B_ * M_];   // per-slice per-point minima (incl |p|^2)
__device__ float g_sums[R1BLOCKS_];

union df2 { unsigned long long u; float2 f; };

__device__ __forceinline__ unsigned long long pack2(float lo, float hi) {
    df2 t; t.f = make_float2(lo, hi); return t.u;
}

// Packed dual-FMA: two f32 lanes in one instruction (Blackwell f32x2 path).
__device__ __forceinline__ unsigned long long fma2(unsigned long long a,
                                                   unsigned long long b,
                                                   unsigned long long c) {
    unsigned long long r;
    asm("fma.rn.f32x2 %0, %1, %2, %3;" : "=l"(r) : "l"(a), "l"(b), "l"(c));
    return r;
}

// ---------------------------------------------------------------------------
// Kernel 1: fused refine (inline, per-slice) + nearest-point partial minima.
// grid = (B, CHUNKS, SLICES) = (4,2,36) = 288 blocks -> 2 CTAs/SM (16 warps/SM).
// smem holds the slice duplicated per lane-pair: sa[j]={xx,yy}, sb[j]={zz,ww}.
// Each thread carries 4 packed pairs (8 pc points) to amortize LDS per pair.
// ---------------------------------------------------------------------------
__global__ __launch_bounds__(THREADS_, 2)
void dist_kernel(const float* __restrict__ mesh, const float* __restrict__ pc) {
    __shared__ ulonglong2 sa[SLICE_];   // {x,x},{y,y}
    __shared__ ulonglong2 sb[SLICE_];   // {z,z},{w,w}  w = |m|^2

    const int b     = blockIdx.x;
    const int chunk = blockIdx.y;
    const int s     = blockIdx.z;

    const int base = s * SLICE_;
    const int cnt  = (base + SLICE_ <= NMESH_) ? SLICE_ : (NMESH_ - base);

    // --- Inline bilinear refine (align_corners, factor 3) for this slice ---
    const float* __restrict__ m0 = mesh + (b * 3 + 0) * H_ * W_;
    const float* __restrict__ m1 = mesh + (b * 3 + 1) * H_ * W_;
    const float* __restrict__ m2 = mesh + (b * 3 + 2) * H_ * W_;

    for (int i = threadIdx.x; i < cnt; i += THREADS_) {
        int idx = base + i;
        int r = idx / OW_;
        int c = idx - r * OW_;
        int y0 = r / FAC_; if (y0 > H_ - 2) y0 = H_ - 2;
        int x0 = c / FAC_; if (x0 > W_ - 2) x0 = W_ - 2;
        float wy = (float)r / (float)FAC_ - (float)y0;
        float wx = (float)c / (float)FAC_ - (float)x0;
        int o00 = y0 * W_ + x0, o01 = o00 + 1, o10 = o00 + W_, o11 = o10 + 1;

        float t0 = m0[o00] * (1.0f - wx) + m0[o01] * wx;
        float u0 = m0[o10] * (1.0f - wx) + m0[o11] * wx;
        float v0 = t0 * (1.0f - wy) + u0 * wy;

        float t1 = m1[o00] * (1.0f - wx) + m1[o01] * wx;
        float u1 = m1[o10] * (1.0f - wx) + m1[o11] * wx;
        float v1 = t1 * (1.0f - wy) + u1 * wy;

        float t2 = m2[o00] * (1.0f - wx) + m2[o01] * wx;
        float u2 = m2[o10] * (1.0f - wx) + m2[o11] * wx;
        float v2 = t2 * (1.0f - wy) + u2 * wy;

        float w = fmaf(v0, v0, fmaf(v1, v1, v2 * v2));

        sa[i] = make_ulonglong2(pack2(v0, v0), pack2(v1, v1));
        sb[i] = make_ulonglong2(pack2(v2, v2), pack2(w, w));
    }
    __syncthreads();

    // --- Load this thread's pc point pairs ---
    const float* __restrict__ px = pc + (b * 3 + 0) * M_;
    const float* __restrict__ py = pc + (b * 3 + 1) * M_;
    const float* __restrict__ pz = pc + (b * 3 + 2) * M_;

    const int q0 = chunk * (THREADS_ * RPT_) + threadIdx.x;   // pair index

    unsigned long long ax2[RPT_], ay2[RPT_], az2[RPT_];
    float pp0[RPT_], pp1[RPT_], b0[RPT_], b1[RPT_];
#pragma unroll
    for (int r = 0; r < RPT_; r++) {
        int q = q0 + r * THREADS_;
        float2 x = *(const float2*)(px + 2 * q);
        float2 y = *(const float2*)(py + 2 * q);
        float2 z = *(const float2*)(pz + 2 * q);
        ax2[r] = pack2(-2.0f * x.x, -2.0f * x.y);
        ay2[r] = pack2(-2.0f * y.x, -2.0f * y.y);
        az2[r] = pack2(-2.0f * z.x, -2.0f * z.y);
        pp0[r] = fmaf(x.x, x.x, fmaf(y.x, y.x, z.x * z.x));
        pp1[r] = fmaf(x.y, x.y, fmaf(y.y, y.y, z.y * z.y));
        b0[r] = FLT_MAX;
        b1[r] = FLT_MAX;
    }

    // --- Hot loop: t = fma2(xx,ax, fma2(yy,ay, fma2(zz,az, ww))); min-fold ---
#pragma unroll 2
    for (int j = 0; j < cnt; j++) {
        ulonglong2 A = sa[j];   // broadcast LDS.128
        ulonglong2 Bv = sb[j];
#pragma unroll
        for (int r = 0; r < RPT_; r++) {
            df2 t;
            t.u = fma2(A.x, ax2[r], fma2(A.y, ay2[r], fma2(Bv.x, az2[r], Bv.y)));
            b0[r] = fminf(b0[r], t.f.x);
            b1[r] = fminf(b1[r], t.f.y);
        }
    }

#pragma unroll
    for (int r = 0; r < RPT_; r++) {
        int q = q0 + r * THREADS_;
        float2 out = make_float2(b0[r] + pp0[r], b1[r] + pp1[r]);
        *(float2*)(g_partial + (s * B_ + b) * M_ + 2 * q) = out;
    }
}

// ---------------------------------------------------------------------------
// Kernel 2: per-point min across slices + per-block deterministic tree sum.
// grid = 64 blocks x 256 threads, one point per thread.
// ---------------------------------------------------------------------------
__global__ __launch_bounds__(THREADS_)
void reduce1_kernel() {
    __shared__ float red[THREADS_];
    const int i = blockIdx.x * THREADS_ + threadIdx.x;   // i < 16384
    float v = g_partial[i];
#pragma unroll
    for (int s = 1; s < SLICES_; s++)
        v = fminf(v, g_partial[s * (B_ * M_) + i]);
    red[threadIdx.x] = v;
    __syncthreads();
#pragma unroll
    for (int off = THREADS_ / 2; off > 0; off >>= 1) {
        if (threadIdx.x < off) red[threadIdx.x] += red[threadIdx.x + off];
        __syncthreads();
    }
    if (threadIdx.x == 0) g_sums[blockIdx.x] = red[0];
}

// ---------------------------------------------------------------------------
// Kernel 3: final deterministic sum of 64 partials + mean.
// ---------------------------------------------------------------------------
__global__ void reduce2_kernel(float* __restrict__ out) {
    __shared__ float red[R1BLOCKS_];
    red[threadIdx.x] = g_sums[threadIdx.x];
    __syncthreads();
#pragma unroll
    for (int off = R1BLOCKS_ / 2; off > 0; off >>= 1) {
        if (threadIdx.x < off) red[threadIdx.x] += red[threadIdx.x + off];
        __syncthreads();
    }
    if (threadIdx.x == 0) out[0] = red[0] / (float)(B_ * M_);
}

// ---------------------------------------------------------------------------
extern "C" void kernel_launch(void* const* d_in, const int* in_sizes, int n_in,
                              void* d_out, int out_size) {
    const float* mesh = (const float*)d_in[0];
    const float* pc   = (const float*)d_in[1];
    float* out = (float*)d_out;

    dim3 grid(B_, CHUNKS_, SLICES_);
    dist_kernel<<<grid, THREADS_>>>(mesh, pc);
    reduce1_kernel<<<R1BLOCKS_, THREADS_>>>();
    reduce2_kernel<<<1, R1BLOCKS_>>>(out);
}

// round 4
// speedup vs baseline: 1.6815x; 1.0563x over previous
#include <cuda_runtime.h>
#include <float.h>

// Shapes (fixed): network_mesh (4,3,32,32) f32 = d_in[0]; pc (4,3,4096) f32 = d_in[1].
// Output: scalar f32 = mean over 4*4096 nearest-refined-mesh squared distances.
#define B_       4
#define H_       32
#define W_       32
#define FAC_     3
#define OH_      94          // (32-1)*3+1
#define OW_      94
#define NMESH_   (OH_ * OW_) // 8836
#define M_       4096
#define SLICES_  56
#define SLICE_   158         // ceil(8836/56); last slice = 146
#define THREADS_ 256
#define RPT_     4           // pc point PAIRS per thread (4 pairs = 8 points)
#define CHUNKS_  2           // 4096 pts / (256 thr * 8 pts)
#define R1BLOCKS_ 64

// Allocation-free scratch.
__device__ float g_partial[SLICES_ * B_ * M_];   // per-slice per-point minima (incl |p|^2)
__device__ float g_sums[R1BLOCKS_];

union df2 { unsigned long long u; float2 f; };

__device__ __forceinline__ unsigned long long pack2(float lo, float hi) {
    df2 t; t.f = make_float2(lo, hi); return t.u;
}

// Packed dual-FMA: two f32 lanes in one instruction (Blackwell f32x2 path).
__device__ __forceinline__ unsigned long long fma2(unsigned long long a,
                                                   unsigned long long b,
                                                   unsigned long long c) {
    unsigned long long r;
    asm("fma.rn.f32x2 %0, %1, %2, %3;" : "=l"(r) : "l"(a), "l"(b), "l"(c));
    return r;
}

// ---------------------------------------------------------------------------
// Kernel 1: fused refine (inline, per-slice) + nearest-point partial minima.
// grid = (B, CHUNKS, SLICES) = (4,2,56) = 448 blocks -> 3 CTAs/SM (24 warps/SM).
// smem holds the slice duplicated per lane-pair: sa[j]={xx,yy}, sb[j]={zz,ww}.
// Each thread carries 4 packed pairs (8 pc points).
// ---------------------------------------------------------------------------
__global__ __launch_bounds__(THREADS_, 3)
void dist_kernel(const float* __restrict__ mesh, const float* __restrict__ pc) {
    __shared__ ulonglong2 sa[SLICE_];   // {x,x},{y,y}
    __shared__ ulonglong2 sb[SLICE_];   // {z,z},{w,w}  w = |m|^2

    const int b     = blockIdx.x;
    const int chunk = blockIdx.y;
    const int s     = blockIdx.z;

    const int base = s * SLICE_;
    const int cnt  = (base + SLICE_ <= NMESH_) ? SLICE_ : (NMESH_ - base);

    // --- Inline bilinear refine (align_corners, factor 3) for this slice ---
    const float* __restrict__ m0 = mesh + (b * 3 + 0) * H_ * W_;
    const float* __restrict__ m1 = mesh + (b * 3 + 1) * H_ * W_;
    const float* __restrict__ m2 = mesh + (b * 3 + 2) * H_ * W_;

    if (threadIdx.x < cnt) {
        int i = threadIdx.x;                 // SLICE_ <= THREADS_, one pass
        int idx = base + i;
        int r = idx / OW_;
        int c = idx - r * OW_;
        int y0 = r / FAC_; if (y0 > H_ - 2) y0 = H_ - 2;
        int x0 = c / FAC_; if (x0 > W_ - 2) x0 = W_ - 2;
        float wy = (float)r / (float)FAC_ - (float)y0;
        float wx = (float)c / (float)FAC_ - (float)x0;
        int o00 = y0 * W_ + x0, o01 = o00 + 1, o10 = o00 + W_, o11 = o10 + 1;

        float t0 = m0[o00] * (1.0f - wx) + m0[o01] * wx;
        float u0 = m0[o10] * (1.0f - wx) + m0[o11] * wx;
        float v0 = t0 * (1.0f - wy) + u0 * wy;

        float t1 = m1[o00] * (1.0f - wx) + m1[o01] * wx;
        float u1 = m1[o10] * (1.0f - wx) + m1[o11] * wx;
        float v1 = t1 * (1.0f - wy) + u1 * wy;

        float t2 = m2[o00] * (1.0f - wx) + m2[o01] * wx;
        float u2 = m2[o10] * (1.0f - wx) + m2[o11] * wx;
        float v2 = t2 * (1.0f - wy) + u2 * wy;

        float w = fmaf(v0, v0, fmaf(v1, v1, v2 * v2));

        sa[i] = make_ulonglong2(pack2(v0, v0), pack2(v1, v1));
        sb[i] = make_ulonglong2(pack2(v2, v2), pack2(w, w));
    }
    __syncthreads();

    // --- Load this thread's pc point pairs ---
    const float* __restrict__ px = pc + (b * 3 + 0) * M_;
    const float* __restrict__ py = pc + (b * 3 + 1) * M_;
    const float* __restrict__ pz = pc + (b * 3 + 2) * M_;

    const int q0 = chunk * (THREADS_ * RPT_) + threadIdx.x;   // pair index

    unsigned long long ax2[RPT_], ay2[RPT_], az2[RPT_];
    float pp0[RPT_], pp1[RPT_], b0[RPT_], b1[RPT_];
#pragma unroll
    for (int r = 0; r < RPT_; r++) {
        int q = q0 + r * THREADS_;
        float2 x = *(const float2*)(px + 2 * q);
        float2 y = *(const float2*)(py + 2 * q);
        float2 z = *(const float2*)(pz + 2 * q);
        ax2[r] = pack2(-2.0f * x.x, -2.0f * x.y);
        ay2[r] = pack2(-2.0f * y.x, -2.0f * y.y);
        az2[r] = pack2(-2.0f * z.x, -2.0f * z.y);
        pp0[r] = fmaf(x.x, x.x, fmaf(y.x, y.x, z.x * z.x));
        pp1[r] = fmaf(x.y, x.y, fmaf(y.y, y.y, z.y * z.y));
        b0[r] = FLT_MAX;
        b1[r] = FLT_MAX;
    }

    // --- Hot loop: t = fma2(xx,ax, fma2(yy,ay, fma2(zz,az, ww))); min-fold ---
#pragma unroll 2
    for (int j = 0; j < cnt; j++) {
        ulonglong2 A = sa[j];   // broadcast LDS.128
        ulonglong2 Bv = sb[j];
#pragma unroll
        for (int r = 0; r < RPT_; r++) {
            df2 t;
            t.u = fma2(A.x, ax2[r], fma2(A.y, ay2[r], fma2(Bv.x, az2[r], Bv.y)));
            b0[r] = fminf(b0[r], t.f.x);
            b1[r] = fminf(b1[r], t.f.y);
        }
    }

#pragma unroll
    for (int r = 0; r < RPT_; r++) {
        int q = q0 + r * THREADS_;
        float2 out = make_float2(b0[r] + pp0[r], b1[r] + pp1[r]);
        *(float2*)(g_partial + (s * B_ + b) * M_ + 2 * q) = out;
    }
}

// ---------------------------------------------------------------------------
// Kernel 2: per-point min across slices + per-block deterministic tree sum.
// grid = 64 blocks x 256 threads, one point per thread.
// ---------------------------------------------------------------------------
__global__ __launch_bounds__(THREADS_)
void reduce1_kernel() {
    __shared__ float red[THREADS_];
    const int i = blockIdx.x * THREADS_ + threadIdx.x;   // i < 16384
    float v = g_partial[i];
#pragma unroll
    for (int s = 1; s < SLICES_; s++)
        v = fminf(v, g_partial[s * (B_ * M_) + i]);
    red[threadIdx.x] = v;
    __syncthreads();
#pragma unroll
    for (int off = THREADS_ / 2; off > 0; off >>= 1) {
        if (threadIdx.x < off) red[threadIdx.x] += red[threadIdx.x + off];
        __syncthreads();
    }
    if (threadIdx.x == 0) g_sums[blockIdx.x] = red[0];
}

// ---------------------------------------------------------------------------
// Kernel 3: final deterministic sum of 64 partials + mean.
// ---------------------------------------------------------------------------
__global__ void reduce2_kernel(float* __restrict__ out) {
    __shared__ float red[R1BLOCKS_];
    red[threadIdx.x] = g_sums[threadIdx.x];
    __syncthreads();
#pragma unroll
    for (int off = R1BLOCKS_ / 2; off > 0; off >>= 1) {
        if (threadIdx.x < off) red[threadIdx.x] += red[threadIdx.x + off];
        __syncthreads();
    }
    if (threadIdx.x == 0) out[0] = red[0] / (float)(B_ * M_);
}

// ---------------------------------------------------------------------------
extern "C" void kernel_launch(void* const* d_in, const int* in_sizes, int n_in,
                              void* d_out, int out_size) {
    const float* mesh = (const float*)d_in[0];
    const float* pc   = (const float*)d_in[1];
    float* out = (float*)d_out;

    dim3 grid(B_, CHUNKS_, SLICES_);
    dist_kernel<<<grid, THREADS_>>>(mesh, pc);
    reduce1_kernel<<<R1BLOCKS_, THREADS_>>>();
    reduce2_kernel<<<1, R1BLOCKS_>>>(out);
}